// round 1
// baseline (speedup 1.0000x reference)
#include <cuda_runtime.h>
#include <cstdint>

// Spatial correlation sampler: out[b, dh*9+dw, h, w] =
//   (1/C) * sum_c in1[b,c,h,w] * in2[b,c,h+dh-4,w+dw-4]   (zero-padded)
// Shapes fixed by the problem: B=8, C=256, H=128, W=256, patch=9.

#define BB   8
#define CC_  256
#define HH   128
#define WW   256
#define RAD  4
#define PATCH 9

#define TH   8            // output rows per block
#define TW   32           // output cols per block
#define CCH  4            // channels per pipeline stage
#define NSTG 2            // double buffer
#define ROWS2 (TH + 2*RAD)        // 16 in2 rows per tile
#define PITCH2 44                  // 11 chunks of 4 floats (TW + 2*RAD = 40, 44 loaded)
#define IN2_CHUNKS (ROWS2 * 11)    // 176 16B-chunks per channel
#define IN1_CHUNKS (TH * TW / 4)   // 64 chunks per channel
#define CH_CHUNKS  (IN2_CHUNKS + IN1_CHUNKS)  // 240
#define CH_FLOATS  (ROWS2*PITCH2 + TH*TW)     // 960 floats per channel
#define TOT_CHUNKS (CCH * CH_CHUNKS)          // 960 chunks per stage
#define NTHREADS 576

__device__ __forceinline__ unsigned smem_u32(const void* p) {
    return (unsigned)__cvta_generic_to_shared(p);
}
__device__ __forceinline__ void cp16(unsigned dst, const void* src, int src_bytes) {
    asm volatile("cp.async.cg.shared.global [%0], [%1], 16, %2;\n"
                 :: "r"(dst), "l"(src), "r"(src_bytes));
}

__global__ void __launch_bounds__(NTHREADS, 1)
corr_kernel(const float* __restrict__ in1,
            const float* __restrict__ in2,
            float* __restrict__ out)
{
    __shared__ __align__(16) float sm[NSTG][CCH * CH_FLOATS];

    const int tid = threadIdx.x;
    const int wg  = tid & 7;          // w-group: 4 pixels each, 8 groups = 32 w
    const int hh  = (tid >> 3) & 7;   // row within tile
    const int dh  = tid >> 6;         // displacement row 0..8

    const int w0 = blockIdx.x * TW;
    const int h0 = blockIdx.y * TH;
    const int b  = blockIdx.z;

    const float* __restrict__ in1b = in1 + (size_t)b * CC_ * HH * WW;
    const float* __restrict__ in2b = in2 + (size_t)b * CC_ * HH * WW;

    float acc[PATCH][4];
#pragma unroll
    for (int dw = 0; dw < PATCH; dw++)
#pragma unroll
        for (int j = 0; j < 4; j++) acc[dw][j] = 0.0f;

    // per-thread constant smem offsets for the compute phase
    const int off_win = (hh + dh) * PITCH2 + wg * 4;           // into in2 region
    const int off_a   = ROWS2 * PITCH2 + hh * TW + wg * 4;     // into in1 region

    // ---- stage loader: issues cp.async for CCH channels starting at s*CCH ----
    auto load_stage = [&](int s) {
        float* buf = sm[s & 1];
        const int c0 = s * CCH;
#pragma unroll
        for (int it = 0; it < 2; it++) {          // 960 chunks / 576 threads
            int i = tid + it * NTHREADS;
            if (i >= TOT_CHUNKS) break;
            int ch = i / CH_CHUNKS;
            int r  = i - ch * CH_CHUNKS;
            const int c = c0 + ch;
            unsigned dst;
            const float* src;
            int sz = 16;
            if (r < IN2_CHUNKS) {
                int row = r / 11;
                int ck  = r - row * 11;
                int gh = h0 - RAD + row;
                int gw = w0 - RAD + ck * 4;
                dst = smem_u32(buf + ch * CH_FLOATS + row * PITCH2 + ck * 4);
                if (gh < 0 || gh >= HH || gw < 0 || gw >= WW) {
                    sz = 0; src = in2b;          // zero-fill, safe dummy address
                } else {
                    src = in2b + ((size_t)c * HH + gh) * WW + gw;
                }
            } else {
                int r2 = r - IN2_CHUNKS;
                int row = r2 >> 3;
                int ck  = r2 & 7;
                src = in1b + ((size_t)c * HH + (h0 + row)) * WW + (w0 + ck * 4);
                dst = smem_u32(buf + ch * CH_FLOATS + ROWS2 * PITCH2 + row * TW + ck * 4);
            }
            cp16(dst, src, sz);
        }
    };

    // ---- compute one resident stage: CCH channels, 36 FFMA each ----
    auto compute_stage = [&](int s) {
        const float* buf = sm[s & 1];
#pragma unroll
        for (int cc = 0; cc < CCH; cc++) {
            const float* chp = buf + cc * CH_FLOATS;
            const float4 a4 = *(const float4*)(chp + off_a);
            const float4* wp = (const float4*)(chp + off_win);
            float4 x0 = wp[0], x1 = wp[1], x2 = wp[2];
            float win[12] = { x0.x, x0.y, x0.z, x0.w,
                              x1.x, x1.y, x1.z, x1.w,
                              x2.x, x2.y, x2.z, x2.w };
            float a[4] = { a4.x, a4.y, a4.z, a4.w };
#pragma unroll
            for (int dw = 0; dw < PATCH; dw++)
#pragma unroll
                for (int j = 0; j < 4; j++)
                    acc[dw][j] = fmaf(a[j], win[j + dw], acc[dw][j]);
        }
    };

    const int NST = CC_ / CCH;  // 64 stages

    load_stage(0);
    asm volatile("cp.async.commit_group;\n");

    for (int s = 0; s < NST; s++) {
        if (s + 1 < NST) {
            load_stage(s + 1);
            asm volatile("cp.async.commit_group;\n");
            asm volatile("cp.async.wait_group 1;\n");
        } else {
            asm volatile("cp.async.wait_group 0;\n");
        }
        __syncthreads();
        compute_stage(s);
        __syncthreads();   // protect stage buffer before it is overwritten
    }

    // ---- epilogue: 9 float4 stores per thread ----
    const float scale = 1.0f / (float)CC_;
    float* outp = out + (((size_t)b * (PATCH * PATCH) + dh * PATCH) * HH + (h0 + hh)) * WW
                      + (w0 + wg * 4);
#pragma unroll
    for (int dw = 0; dw < PATCH; dw++) {
        float4 v;
        v.x = acc[dw][0] * scale;
        v.y = acc[dw][1] * scale;
        v.z = acc[dw][2] * scale;
        v.w = acc[dw][3] * scale;
        *(float4*)(outp + (size_t)dw * HH * WW) = v;
    }
}

extern "C" void kernel_launch(void* const* d_in, const int* in_sizes, int n_in,
                              void* d_out, int out_size)
{
    const float* in1 = (const float*)d_in[0];
    const float* in2 = (const float*)d_in[1];
    float* out = (float*)d_out;

    dim3 grid(WW / TW, HH / TH, BB);   // 8 x 16 x 8 = 1024 blocks
    dim3 block(NTHREADS);
    corr_kernel<<<grid, block>>>(in1, in2, out);
}